// round 3
// baseline (speedup 1.0000x reference)
#include <cuda_runtime.h>
#include <cstdint>

// FP32->FP16 gate-level emulation, collapsed to integer logic. v2:
//   - input:  8x LDG.128 per warp (front-batched, MLP=8), PRMT/multiply bit-pack,
//             shfl_xor OR-butterfly to assemble one uint32 word per row.
//   - compute: integer fp32->fp16 RNE conversion (bit-exact vs gate algebra).
//   - output: shfl redistribution + compile-time-mask selects, float4 stores.
// Streaming cache hints (.cs) on both loads and stores.

__device__ __forceinline__ unsigned convert_row(unsigned w) {
    unsigned s = w >> 31;
    unsigned e = (w >> 23) & 0xFFu;
    unsigned m = w & 0x7FFFFFu;

    unsigned h;
    if (e == 255u) {
        h = (s << 15) | (m ? 0x7E00u : 0x7C00u);       // nan / inf
    } else if (e < 113u) {
        h = 0u;                                         // underflow -> +0
    } else if (e > 142u) {
        h = (s << 15) | 0x7C00u;                        // overflow -> inf
    } else {
        unsigned mant10 = m >> 13;
        unsigned L = mant10 & 1u;
        unsigned R = (m >> 12) & 1u;
        unsigned S = (m & 0xFFFu) != 0u;
        unsigned round_up = R & (S | L);
        unsigned mant_r = mant10 + round_up;            // 11-bit
        unsigned carry = mant_r >> 10;
        unsigned mant_f = mant_r & 0x3FFu;
        unsigned exp5 = (e - 112u + carry) & 31u;       // 5-bit wrap add
        h = (s << 15) | (exp5 << 10) | mant_f;
    }
    return h;
}

__global__ void __launch_bounds__(256)
fp32_to_fp16_bits_kernel(const float4* __restrict__ in,
                         float4* __restrict__ out,
                         int nrows) {
    const int lane = threadIdx.x & 31;
    const int warpId = (int)((blockIdx.x * blockDim.x + threadIdx.x) >> 5);
    const int rowbase = warpId * 32;
    if (rowbase >= nrows) return;

    // ---- input: 8 coalesced LDG.128 per warp, front-batched ----
    const float4* ip4 = in + (size_t)rowbase * 8;   // 32 floats/row = 8 float4
    float4 v[8];
#pragma unroll
    for (int i = 0; i < 8; i++) v[i] = __ldcs(ip4 + (size_t)i * 32 + lane);

    // ---- pack: build pulse-order uint32 word per row, lane r owns row r ----
    const unsigned shift = (lane & 7) * 4;   // nibble position within row word
    unsigned myword = 0u;
#pragma unroll
    for (int i = 0; i < 8; i++) {
        unsigned ux = __float_as_uint(v[i].x);
        unsigned uy = __float_as_uint(v[i].y);
        unsigned uz = __float_as_uint(v[i].z);
        unsigned uw = __float_as_uint(v[i].w);
        // gather high bytes (0x3F for 1.0f, 0x00 for 0.0f) into one word
        unsigned p0 = __byte_perm(ux, uy, 0x0073);   // {a.b3, b.b3, 0, 0}
        unsigned p1 = __byte_perm(uz, uw, 0x0073);
        unsigned bytes = __byte_perm(p0, p1, 0x5410); // {x.b3, y.b3, z.b3, w.b3}
        unsigned spread = bytes & 0x01010101u;        // bit0 of 0x3F is 1
        unsigned nib = (spread * 0x01020408u) >> 24;  // b0|b1<<1|b2<<2|b3<<3
        unsigned word = nib << shift;                 // pulse positions 4*(l&7)..+3
        // OR-reduce across the 8-lane group (lanes sharing l>>3)
        word |= __shfl_xor_sync(0xFFFFFFFFu, word, 1);
        word |= __shfl_xor_sync(0xFFFFFFFFu, word, 2);
        word |= __shfl_xor_sync(0xFFFFFFFFu, word, 4);
        // row i*4 + k lives (replicated) in lanes 8k..8k+7; lane l wants row l
        unsigned tmp = __shfl_sync(0xFFFFFFFFu, word, (lane & 3) * 8);
        if ((lane >> 2) == i) myword = tmp;
    }
    // pulse order -> IEEE754 layout (pulse 0 = sign = bit 31)
    unsigned w = __brev(myword);

    // ---- compute ----
    unsigned h = convert_row(w);

    // ---- output: 128 float4 per warp, coalesced, streaming stores ----
    float4* op = out + (size_t)rowbase * 4;          // 16 floats/row = 4 float4
    const int k0 = 4 * (lane & 3);
#pragma unroll
    for (int i = 0; i < 4; i++) {
        unsigned hr = __shfl_sync(0xFFFFFFFFu, h, 8 * i + (lane >> 2));
        unsigned hs = hr << (16 + k0);               // bit (15-k0) -> bit 31
        float4 f;
        f.x = (hs & 0x80000000u) ? 1.0f : 0.0f;
        f.y = (hs & 0x40000000u) ? 1.0f : 0.0f;
        f.z = (hs & 0x20000000u) ? 1.0f : 0.0f;
        f.w = (hs & 0x10000000u) ? 1.0f : 0.0f;
        __stcs(op + (size_t)i * 32 + lane, f);
    }
}

extern "C" void kernel_launch(void* const* d_in, const int* in_sizes, int n_in,
                              void* d_out, int out_size) {
    const float4* in = (const float4*)d_in[0];
    float4* out = (float4*)d_out;

    int nrows = in_sizes[0] / 32;           // 2048*1024 = 2097152
    int nwarps = (nrows + 31) / 32;
    int threads = 256;
    int blocks = (nwarps + 7) / 8;

    fp32_to_fp16_bits_kernel<<<blocks, threads>>>(in, out, nrows);
}

// round 4
// speedup vs baseline: 1.0144x; 1.0144x over previous
#include <cuda_runtime.h>
#include <cstdint>

// FP32->FP16 gate-level emulation, collapsed to integer logic. v3:
//   - 64 rows per warp, 16 front-batched LDG.128 (MLP=16/thread) for deeper
//     memory pipelining.
//   - PRMT/multiply bit-pack + shfl_xor OR-butterfly transpose (per 32-row half).
//   - integer fp32->fp16 RNE conversion (bit-exact vs the gate algebra on {0,1}).
//   - branch-free bit->float via arithmetic shift + AND (no predicates).
//   - streaming cache hints on loads and stores.

__device__ __forceinline__ unsigned convert_row(unsigned w) {
    unsigned s = w >> 31;
    unsigned e = (w >> 23) & 0xFFu;
    unsigned m = w & 0x7FFFFFu;

    unsigned h;
    if (e == 255u) {
        h = (s << 15) | (m ? 0x7E00u : 0x7C00u);       // nan / inf
    } else if (e < 113u) {
        h = 0u;                                         // underflow -> +0
    } else if (e > 142u) {
        h = (s << 15) | 0x7C00u;                        // overflow -> inf
    } else {
        unsigned mant10 = m >> 13;
        unsigned L = mant10 & 1u;
        unsigned R = (m >> 12) & 1u;
        unsigned S = (m & 0xFFFu) != 0u;
        unsigned round_up = R & (S | L);
        unsigned mant_r = mant10 + round_up;            // 11-bit
        unsigned carry = mant_r >> 10;
        unsigned mant_f = mant_r & 0x3FFu;
        unsigned exp5 = (e - 112u + carry) & 31u;       // 5-bit wrap add
        h = (s << 15) | (exp5 << 10) | mant_f;
    }
    return h;
}

// Pack one 32-row block: v[8] are this lane's float4s of the block
// (layout: float4 index i*32+lane over a 32x8 float4 row-major tile).
// Returns the IEEE-layout uint32 word of row `lane`.
__device__ __forceinline__ unsigned pack_block(const float4* v, int lane) {
    const unsigned shift = (lane & 7) * 4;   // nibble position within row word
    unsigned myword = 0u;
#pragma unroll
    for (int i = 0; i < 8; i++) {
        unsigned ux = __float_as_uint(v[i].x);
        unsigned uy = __float_as_uint(v[i].y);
        unsigned uz = __float_as_uint(v[i].z);
        unsigned uw = __float_as_uint(v[i].w);
        unsigned p0 = __byte_perm(ux, uy, 0x0073);     // {x.b3, y.b3, 0, 0}
        unsigned p1 = __byte_perm(uz, uw, 0x0073);
        unsigned bytes = __byte_perm(p0, p1, 0x5410);  // {x.b3,y.b3,z.b3,w.b3}
        unsigned spread = bytes & 0x01010101u;         // 1.0f has byte 0x3F
        unsigned nib = (spread * 0x01020408u) >> 24;   // 4 bits gathered
        unsigned word = nib << shift;
        // OR-reduce across the 8-lane group (lanes sharing l>>3)
        word |= __shfl_xor_sync(0xFFFFFFFFu, word, 1);
        word |= __shfl_xor_sync(0xFFFFFFFFu, word, 2);
        word |= __shfl_xor_sync(0xFFFFFFFFu, word, 4);
        // rows i*4+k replicated in lanes 8k..8k+7; lane l wants row l
        unsigned tmp = __shfl_sync(0xFFFFFFFFu, word, (lane & 3) * 8);
        if ((lane >> 2) == i) myword = tmp;
    }
    return __brev(myword);   // pulse order -> IEEE layout (pulse0 = bit31)
}

// Store one 32-row block's fp16 bit-vectors; h = this lane's row result.
__device__ __forceinline__ void store_block(float4* op, unsigned h, int lane) {
    const int k0 = 4 * (lane & 3);
#pragma unroll
    for (int i = 0; i < 4; i++) {
        unsigned hr = __shfl_sync(0xFFFFFFFFu, h, 8 * i + (lane >> 2));
        unsigned hs = hr << (16 + k0);                 // bit (15-k0) -> bit 31
        float4 f;
        f.x = __uint_as_float(((unsigned)((int)(hs)      >> 31)) & 0x3F800000u);
        f.y = __uint_as_float(((unsigned)((int)(hs << 1) >> 31)) & 0x3F800000u);
        f.z = __uint_as_float(((unsigned)((int)(hs << 2) >> 31)) & 0x3F800000u);
        f.w = __uint_as_float(((unsigned)((int)(hs << 3) >> 31)) & 0x3F800000u);
        __stcs(op + (size_t)i * 32 + lane, f);
    }
}

__global__ void __launch_bounds__(128)
fp32_to_fp16_bits_kernel(const float4* __restrict__ in,
                         float4* __restrict__ out,
                         int nrows) {
    const int lane = threadIdx.x & 31;
    const int warpId = (int)((blockIdx.x * blockDim.x + threadIdx.x) >> 5);
    const int rowbase = warpId * 64;                  // 64 rows per warp
    if (rowbase >= nrows) return;

    const float4* ipA = in + (size_t)rowbase * 8;     // rows rowbase..+31
    const float4* ipB = ipA + 32 * 8;                 // rows rowbase+32..+63

    // ---- 16 front-batched LDG.128 (MLP = 16 per thread) ----
    float4 vA[8], vB[8];
#pragma unroll
    for (int i = 0; i < 8; i++) vA[i] = __ldcs(ipA + (size_t)i * 32 + lane);
#pragma unroll
    for (int i = 0; i < 8; i++) vB[i] = __ldcs(ipB + (size_t)i * 32 + lane);

    // ---- pack + convert ----
    unsigned wA = pack_block(vA, lane);
    unsigned hA = convert_row(wA);
    unsigned wB = pack_block(vB, lane);
    unsigned hB = convert_row(wB);

    // ---- output ----
    float4* opA = out + (size_t)rowbase * 4;
    float4* opB = opA + 32 * 4;
    store_block(opA, hA, lane);
    store_block(opB, hB, lane);
}

extern "C" void kernel_launch(void* const* d_in, const int* in_sizes, int n_in,
                              void* d_out, int out_size) {
    const float4* in = (const float4*)d_in[0];
    float4* out = (float4*)d_out;

    int nrows = in_sizes[0] / 32;            // 2048*1024 = 2097152
    int nwarps = (nrows + 63) / 64;          // one warp per 64 rows
    int threads = 128;                       // 4 warps per block
    int blocks = (nwarps + 3) / 4;

    fp32_to_fp16_bits_kernel<<<blocks, threads>>>(in, out, nrows);
}